// round 12
// baseline (speedup 1.0000x reference)
#include <cuda_runtime.h>

#define DDIM 4096
#define NTHREADS 512
#define GRID 148
#define R4 4      // rows per group (A/B), 8 rows per iteration
#define NBUF 3

// ---------------------------------------------------------------------------
// Compact-WY form of 8 sequential Householder reflections:
//   x_out = x - U d,  d = S c,  c = U^T x,  S = 2*(I+2L)^{-1}, U normalized.
//
// Persistent kernel, 1 CTA/SM. Each thread holds its 8 elements of all 8
// normalized u vectors in registers (64 regs) -> zero u smem traffic.
// X streams through a 3-buffer cp.async ring (per-thread private slots).
// Interleaved A/B schedule (8 rows/iter, 3 barriers):
//   dots(A) -> bar -> [w0 finish A || dots(B)] -> bar
//   -> [w1 finish B || update+store A, prefetch] -> bar -> update+store B.
// smem: xbuf[3][4*4096] | wsumA[512] | wsumB[512] | dshA[64] | dshB[64]
//       | Ssh[64] | gsh[36] | rn[8]
// ---------------------------------------------------------------------------
extern __shared__ float smem[];

typedef unsigned long long u64;

__device__ __forceinline__ u64 ffma2(u64 a, u64 b, u64 c) {
    u64 d;
    asm("fma.rn.f32x2 %0, %1, %2, %3;" : "=l"(d) : "l"(a), "l"(b), "l"(c));
    return d;
}
__device__ __forceinline__ u64 pack2(float lo, float hi) {
    u64 d;
    asm("mov.b64 %0, {%1, %2};" : "=l"(d) : "f"(lo), "f"(hi));
    return d;
}
__device__ __forceinline__ void unpack2(u64 p, float& lo, float& hi) {
    asm("mov.b64 {%0, %1}, %2;" : "=f"(lo), "=f"(hi) : "l"(p));
}
__device__ __forceinline__ int tri_idx(int a, int b) {
    return a * (17 - a) / 2 + (b - a);  // packed upper-tri [36], a <= b
}

__global__ void __launch_bounds__(NTHREADS, 1)
hra_kernel(const float* __restrict__ X, const float* __restrict__ hra_u,
           float* __restrict__ Y, int nq8) {
    float* xbuf  = smem;                          // 3 * 4*4096
    float* wsumA = xbuf + NBUF * R4 * DDIM;       // 16*32
    float* wsumB = wsumA + 16 * 32;               // 16*32
    float* dshA  = wsumB + 16 * 32;               // 64 (32 u64)
    float* dshB  = dshA + 64;                     // 64
    float* Ssh   = dshB + 64;                     // 64
    float* gsh   = Ssh + 64;                      // 36
    float* rn    = gsh + 36;                      // 8

    const int tid  = threadIdx.x;
    const int lane = tid & 31;
    const int warp = tid >> 5;

    // ---------------- Phase 0: Gram + S + per-thread u registers ----------
    if (tid < 36) gsh[tid] = 0.f;
    __syncthreads();
    {
        float acc[36];
#pragma unroll
        for (int t = 0; t < 36; t++) acc[t] = 0.f;
        for (int k = tid; k < DDIM; k += NTHREADS) {
            float4 a = reinterpret_cast<const float4*>(hra_u)[k * 2];
            float4 b = reinterpret_cast<const float4*>(hra_u)[k * 2 + 1];
            float v[8] = {a.x, a.y, a.z, a.w, b.x, b.y, b.z, b.w};
            int t = 0;
#pragma unroll
            for (int i = 0; i < 8; i++)
#pragma unroll
                for (int j = i; j < 8; j++)
                    acc[t++] += v[i] * v[j];
        }
#pragma unroll
        for (int t = 0; t < 36; t++) {
#pragma unroll
            for (int o = 16; o > 0; o >>= 1)
                acc[t] += __shfl_xor_sync(0xffffffffu, acc[t], o);
        }
        if (lane == 0)
            for (int t = 0; t < 36; t++) atomicAdd(&gsh[t], acc[t]);
    }
    __syncthreads();
    if (tid < 8) rn[tid] = rsqrtf(gsh[tri_idx(tid, tid)]);
    __syncthreads();
    if (tid < 8) {
        const int c = tid;  // column c of S: solve (I + 2L) x = 2 e_c
        float x[8];
#pragma unroll
        for (int i = 0; i < 8; i++) {
            float s = (i == c) ? 2.f : 0.f;
            for (int j = 0; j < i; j++) {
                float gji = gsh[tri_idx(j, i)] * rn[j] * rn[i];
                s -= 2.f * gji * x[j];
            }
            x[i] = s;
            Ssh[i * 8 + c] = x[i];
        }
    }
    __syncthreads();

    // per-thread u regs: elements [4*tid,4*tid+4) and [2048+4*tid, +4)
    u64 up[8][4];
    {
        const float4* hu4 = reinterpret_cast<const float4*>(hra_u);
#pragma unroll
        for (int c = 0; c < 2; c++) {
            float uu[4][8];
#pragma unroll
            for (int e = 0; e < 4; e++) {
                int k = c * 2048 + 4 * tid + e;
                float4 t0 = hu4[k * 2 + 0];
                float4 t1 = hu4[k * 2 + 1];
                uu[e][0] = t0.x; uu[e][1] = t0.y; uu[e][2] = t0.z; uu[e][3] = t0.w;
                uu[e][4] = t1.x; uu[e][5] = t1.y; uu[e][6] = t1.z; uu[e][7] = t1.w;
            }
#pragma unroll
            for (int i = 0; i < 8; i++) {
                float r = rn[i];
                up[i][c * 2 + 0] = pack2(uu[0][i] * r, uu[1][i] * r);
                up[i][c * 2 + 1] = pack2(uu[2][i] * r, uu[3][i] * r);
            }
        }
    }

    // ---------------- Phase 1: main loop (8 rows / iteration) --------------
    const int t_self = (int)(__brev((unsigned)lane) >> 27);  // bitrev5(lane)
    const unsigned xb_base = (unsigned)__cvta_generic_to_shared(xbuf);
    const unsigned BUF_BYTES = R4 * DDIM * 4u;

#define PREFETCH4(buf, rowbase4)                                              \
    do {                                                                      \
        const float4* xg = reinterpret_cast<const float4*>(X) + (rowbase4);   \
        _Pragma("unroll")                                                     \
        for (int r = 0; r < R4; r++) {                                        \
            _Pragma("unroll")                                                 \
            for (int h = 0; h < 2; h++) {                                     \
                unsigned s = xb_base + (buf) * BUF_BYTES                      \
                           + (unsigned)(r * 1024 + h * NTHREADS + tid) * 16u; \
                const float4* g = xg + (r * 1024 + h * NTHREADS + tid);       \
                asm volatile("cp.async.cg.shared.global [%0], [%1], 16;"      \
                             :: "r"(s), "l"(g));                              \
            }                                                                 \
        }                                                                     \
        asm volatile("cp.async.commit_group;");                               \
    } while (0)

    int q = blockIdx.x;
    if (q >= nq8) return;

    // prologue: A(q) -> buf0, B(q) -> buf1
    PREFETCH4(0, (size_t)q * 8192);
    PREFETCH4(1, (size_t)q * 8192 + 4096);

    int ba = 0, bb = 1, bs = 2;
    for (; q < nq8; q += GRID) {
        int qn = q + GRID;
        int qc = qn < nq8 ? qn : q;

        // prefetch A(next) into spare
        PREFETCH4(bs, (size_t)qc * 8192);

        // A(q) guaranteed done when <=2 newest (B(q), A(next)) pending
        asm volatile("cp.async.wait_group 2;");
        const ulonglong2* xa2 =
            reinterpret_cast<const ulonglong2*>(xbuf + ba * (R4 * DDIM));

        // ---- dots(A) ----
        float val[32];
#pragma unroll
        for (int r = 0; r < R4; r++) {
            ulonglong2 xa = xa2[r * 1024 + tid];
            ulonglong2 xc = xa2[r * 1024 + tid + NTHREADS];
#pragma unroll
            for (int i = 0; i < 8; i++) {
                u64 a0 = ffma2(xa.x, up[i][0], 0ull);
                u64 a1 = ffma2(xa.y, up[i][1], 0ull);
                a0 = ffma2(xc.x, up[i][2], a0);
                a1 = ffma2(xc.y, up[i][3], a1);
                float l0, h0, l1, h1;
                unpack2(a0, l0, h0);
                unpack2(a1, l1, h1);
                val[r * 8 + i] = (l0 + h0) + (l1 + h1);
            }
        }
#pragma unroll
        for (int s = 0; s < 5; s++) {
            const int m = 1 << s;
            const int h = 16 >> s;
#pragma unroll
            for (int k = 0; k < h; k++) {
                float send = (lane & m) ? val[k] : val[k + h];
                float rec  = __shfl_xor_sync(0xffffffffu, send, m);
                float keep = (lane & m) ? val[k + h] : val[k];
                val[k] = keep + rec;
            }
        }
        wsumA[warp * 32 + t_self] = val[0];
        __syncthreads();  // bar1: wsumA ready

        // warp0 finishes A while others start dots(B)
        if (warp == 0) {
            float c = 0.f;
#pragma unroll
            for (int w = 0; w < 16; w++) c += wsumA[w * 32 + lane];
            const int i = lane & 7;
            float d = 0.f;
#pragma unroll
            for (int j = 0; j < 8; j++) {
                float cj = __shfl_sync(0xffffffffu, c, (lane & 24) + j);
                d += Ssh[i * 8 + j] * cj;
            }
            reinterpret_cast<u64*>(dshA)[lane] = pack2(-d, -d);
        }

        // B(q) guaranteed done when <=1 newest (A(next)) pending
        asm volatile("cp.async.wait_group 1;");
        const ulonglong2* xb2 =
            reinterpret_cast<const ulonglong2*>(xbuf + bb * (R4 * DDIM));

        // ---- dots(B) ----
#pragma unroll
        for (int r = 0; r < R4; r++) {
            ulonglong2 xa = xb2[r * 1024 + tid];
            ulonglong2 xc = xb2[r * 1024 + tid + NTHREADS];
#pragma unroll
            for (int i = 0; i < 8; i++) {
                u64 a0 = ffma2(xa.x, up[i][0], 0ull);
                u64 a1 = ffma2(xa.y, up[i][1], 0ull);
                a0 = ffma2(xc.x, up[i][2], a0);
                a1 = ffma2(xc.y, up[i][3], a1);
                float l0, h0, l1, h1;
                unpack2(a0, l0, h0);
                unpack2(a1, l1, h1);
                val[r * 8 + i] = (l0 + h0) + (l1 + h1);
            }
        }
#pragma unroll
        for (int s = 0; s < 5; s++) {
            const int m = 1 << s;
            const int h = 16 >> s;
#pragma unroll
            for (int k = 0; k < h; k++) {
                float send = (lane & m) ? val[k] : val[k + h];
                float rec  = __shfl_xor_sync(0xffffffffu, send, m);
                float keep = (lane & m) ? val[k + h] : val[k];
                val[k] = keep + rec;
            }
        }
        wsumB[warp * 32 + t_self] = val[0];
        __syncthreads();  // bar2: dshA + wsumB ready

        // warp1 finishes B while others update A
        if (warp == 1) {
            float c = 0.f;
#pragma unroll
            for (int w = 0; w < 16; w++) c += wsumB[w * 32 + lane];
            const int i = lane & 7;
            float d = 0.f;
#pragma unroll
            for (int j = 0; j < 8; j++) {
                float cj = __shfl_sync(0xffffffffu, c, (lane & 24) + j);
                d += Ssh[i * 8 + j] * cj;
            }
            reinterpret_cast<u64*>(dshB)[lane] = pack2(-d, -d);
        }

        // ---- update + store A ----
        {
            const ulonglong2* dq = reinterpret_cast<const ulonglong2*>(dshA);
            float4* y4 = reinterpret_cast<float4*>(Y) + (size_t)q * 8192;
#pragma unroll
            for (int r = 0; r < R4; r++) {
                ulonglong2 p0 = dq[r * 4 + 0];
                ulonglong2 p1 = dq[r * 4 + 1];
                ulonglong2 p2 = dq[r * 4 + 2];
                ulonglong2 p3 = dq[r * 4 + 3];
                u64 nd[8] = {p0.x, p0.y, p1.x, p1.y, p2.x, p2.y, p3.x, p3.y};
                ulonglong2 xa = xa2[r * 1024 + tid];
                ulonglong2 xc = xa2[r * 1024 + tid + NTHREADS];
                u64 w0 = xa.x, w1 = xa.y, w2 = xc.x, w3 = xc.y;
#pragma unroll
                for (int i = 0; i < 8; i++) {
                    w0 = ffma2(nd[i], up[i][0], w0);
                    w1 = ffma2(nd[i], up[i][1], w1);
                    w2 = ffma2(nd[i], up[i][2], w2);
                    w3 = ffma2(nd[i], up[i][3], w3);
                }
                float4 o0, o1;
                unpack2(w0, o0.x, o0.y); unpack2(w1, o0.z, o0.w);
                unpack2(w2, o1.x, o1.y); unpack2(w3, o1.z, o1.w);
                __stcs(&y4[r * 1024 + tid], o0);
                __stcs(&y4[r * 1024 + tid + NTHREADS], o1);
            }
        }

        // prefetch B(next) into A's buffer (private slots -> no hazard)
        PREFETCH4(ba, (size_t)qc * 8192 + 4096);

        __syncthreads();  // bar3: dshB ready

        // ---- update + store B ----
        {
            const ulonglong2* dq = reinterpret_cast<const ulonglong2*>(dshB);
            float4* y4 = reinterpret_cast<float4*>(Y) + (size_t)q * 8192 + 4096;
#pragma unroll
            for (int r = 0; r < R4; r++) {
                ulonglong2 p0 = dq[r * 4 + 0];
                ulonglong2 p1 = dq[r * 4 + 1];
                ulonglong2 p2 = dq[r * 4 + 2];
                ulonglong2 p3 = dq[r * 4 + 3];
                u64 nd[8] = {p0.x, p0.y, p1.x, p1.y, p2.x, p2.y, p3.x, p3.y};
                ulonglong2 xa = xb2[r * 1024 + tid];
                ulonglong2 xc = xb2[r * 1024 + tid + NTHREADS];
                u64 w0 = xa.x, w1 = xa.y, w2 = xc.x, w3 = xc.y;
#pragma unroll
                for (int i = 0; i < 8; i++) {
                    w0 = ffma2(nd[i], up[i][0], w0);
                    w1 = ffma2(nd[i], up[i][1], w1);
                    w2 = ffma2(nd[i], up[i][2], w2);
                    w3 = ffma2(nd[i], up[i][3], w3);
                }
                float4 o0, o1;
                unpack2(w0, o0.x, o0.y); unpack2(w1, o0.z, o0.w);
                unpack2(w2, o1.x, o1.y); unpack2(w3, o1.z, o1.w);
                __stcs(&y4[r * 1024 + tid], o0);
                __stcs(&y4[r * 1024 + tid + NTHREADS], o1);
            }
        }

        // rotate buffers: A' = spare (holds A(next)), B' = old A (B(next)),
        // spare' = old B (free)
        int t = bs; bs = bb; bb = ba; ba = t;
    }
#undef PREFETCH4
}

extern "C" void kernel_launch(void* const* d_in, const int* in_sizes, int n_in,
                              void* d_out, int out_size) {
    const float* X = (const float*)d_in[0];      // (4, 2048, 4096) fp32
    const float* hra_u = (const float*)d_in[1];  // (4096, 8) fp32
    float* Y = (float*)d_out;

    const int nrows = in_sizes[0] / DDIM;        // 8192
    const int nq8 = nrows / 8;                   // 1024 (8 rows per iteration)

    const size_t smem_bytes =
        (NBUF * R4 * DDIM + 2 * 16 * 32 + 2 * 64 + 64 + 36 + 8) * sizeof(float);
    cudaFuncSetAttribute(hra_kernel,
                         cudaFuncAttributeMaxDynamicSharedMemorySize,
                         (int)smem_bytes);

    hra_kernel<<<GRID, NTHREADS, smem_bytes>>>(X, hra_u, Y, nq8);
}

// round 13
// speedup vs baseline: 1.0507x; 1.0507x over previous
#include <cuda_runtime.h>

#define DDIM 4096
#define NTHREADS 512
#define GRID 148
#define R4 4      // rows per iteration
#define NBUF 3    // cp.async pipeline depth

// ---------------------------------------------------------------------------
// Compact-WY form of 8 sequential Householder reflections:
//   x_out = x - U d,  d = S c,  c = U^T x,  S = 2*(I+2L)^{-1}, U normalized.
//
// Persistent kernel, 1 CTA/SM. Each thread holds its 8 elements of all 8
// normalized u vectors in registers (64 regs) -> zero u smem traffic.
// X streams through a triple-buffered cp.async ring and is pulled into
// registers ONCE per iteration (per-row 9-shfl butterfly keeps val at 8
// regs, freeing room for x to stay resident through the update).
// Schedule per iteration (R10 structure): dots+butterfly -> bar ->
// warp0 finish -> bar -> update(regs) + streaming store.
// smem: xbuf[3][4*4096] | wsum[16*32] | dsh2[64] | Ssh[64] | gsh[36] | rn[8]
// ---------------------------------------------------------------------------
extern __shared__ float smem[];

typedef unsigned long long u64;

__device__ __forceinline__ u64 ffma2(u64 a, u64 b, u64 c) {
    u64 d;
    asm("fma.rn.f32x2 %0, %1, %2, %3;" : "=l"(d) : "l"(a), "l"(b), "l"(c));
    return d;
}
__device__ __forceinline__ u64 pack2(float lo, float hi) {
    u64 d;
    asm("mov.b64 %0, {%1, %2};" : "=l"(d) : "f"(lo), "f"(hi));
    return d;
}
__device__ __forceinline__ void unpack2(u64 p, float& lo, float& hi) {
    asm("mov.b64 {%0, %1}, %2;" : "=f"(lo), "=f"(hi) : "l"(p));
}
__device__ __forceinline__ int tri_idx(int a, int b) {
    return a * (17 - a) / 2 + (b - a);  // packed upper-tri [36], a <= b
}

__global__ void __launch_bounds__(NTHREADS, 1)
hra_kernel(const float* __restrict__ X, const float* __restrict__ hra_u,
           float* __restrict__ Y, int nq) {
    float* xbuf = smem;                         // 3 * 4*4096
    float* wsum = xbuf + NBUF * R4 * DDIM;      // 16*32
    float* dsh2 = wsum + 16 * 32;               // 64 (32 u64), 16B-aligned
    float* Ssh  = dsh2 + 64;                    // 64
    float* gsh  = Ssh + 64;                     // 36
    float* rn   = gsh + 36;                     // 8

    const int tid  = threadIdx.x;
    const int lane = tid & 31;
    const int warp = tid >> 5;

    // ---------------- Phase 0: Gram + S + per-thread u registers ----------
    if (tid < 36) gsh[tid] = 0.f;
    __syncthreads();
    {
        float acc[36];
#pragma unroll
        for (int t = 0; t < 36; t++) acc[t] = 0.f;
        for (int k = tid; k < DDIM; k += NTHREADS) {
            float4 a = reinterpret_cast<const float4*>(hra_u)[k * 2];
            float4 b = reinterpret_cast<const float4*>(hra_u)[k * 2 + 1];
            float v[8] = {a.x, a.y, a.z, a.w, b.x, b.y, b.z, b.w};
            int t = 0;
#pragma unroll
            for (int i = 0; i < 8; i++)
#pragma unroll
                for (int j = i; j < 8; j++)
                    acc[t++] += v[i] * v[j];
        }
#pragma unroll
        for (int t = 0; t < 36; t++) {
#pragma unroll
            for (int o = 16; o > 0; o >>= 1)
                acc[t] += __shfl_xor_sync(0xffffffffu, acc[t], o);
        }
        if (lane == 0)
            for (int t = 0; t < 36; t++) atomicAdd(&gsh[t], acc[t]);
    }
    __syncthreads();
    if (tid < 8) rn[tid] = rsqrtf(gsh[tri_idx(tid, tid)]);
    __syncthreads();
    if (tid < 8) {
        const int c = tid;  // column c of S: solve (I + 2L) x = 2 e_c
        float x[8];
#pragma unroll
        for (int i = 0; i < 8; i++) {
            float s = (i == c) ? 2.f : 0.f;
            for (int j = 0; j < i; j++) {
                float gji = gsh[tri_idx(j, i)] * rn[j] * rn[i];
                s -= 2.f * gji * x[j];
            }
            x[i] = s;
            Ssh[i * 8 + c] = x[i];
        }
    }
    __syncthreads();  // rn, Ssh ready

    // per-thread u registers: elements [4*tid, 4*tid+4) (chunk 0) and
    // [2048+4*tid, 2048+4*tid+4) (chunk 1) of each normalized vector.
    u64 up[8][4];
    {
        const float4* hu4 = reinterpret_cast<const float4*>(hra_u);
#pragma unroll
        for (int c = 0; c < 2; c++) {
            float uu[4][8];
#pragma unroll
            for (int e = 0; e < 4; e++) {
                int k = c * 2048 + 4 * tid + e;
                float4 t0 = hu4[k * 2 + 0];
                float4 t1 = hu4[k * 2 + 1];
                uu[e][0] = t0.x; uu[e][1] = t0.y; uu[e][2] = t0.z; uu[e][3] = t0.w;
                uu[e][4] = t1.x; uu[e][5] = t1.y; uu[e][6] = t1.z; uu[e][7] = t1.w;
            }
#pragma unroll
            for (int i = 0; i < 8; i++) {
                float r = rn[i];
                up[i][c * 2 + 0] = pack2(uu[0][i] * r, uu[1][i] * r);
                up[i][c * 2 + 1] = pack2(uu[2][i] * r, uu[3][i] * r);
            }
        }
    }

    // ---------------- Phase 1: main loop (4 rows / iteration) --------------
    // bitrev3 of lane's low 3 bits: value index this lane ends with
    const int br3 = ((lane & 1) << 2) | (lane & 2) | ((lane >> 2) & 1);
    const unsigned xb_base = (unsigned)__cvta_generic_to_shared(xbuf);
    const unsigned BUF_BYTES = R4 * DDIM * 4u;

    int q = blockIdx.x;
    if (q >= nq) return;

    // prologue: prefetch q -> buf0, q+GRID -> buf1
#pragma unroll
    for (int pb = 0; pb < 2; pb++) {
        int qp = q + pb * GRID;
        int qc = qp < nq ? qp : q;
        const float4* xg = reinterpret_cast<const float4*>(X) + (size_t)qc * 4096;
#pragma unroll
        for (int r = 0; r < R4; r++) {
#pragma unroll
            for (int h = 0; h < 2; h++) {
                unsigned s = xb_base + pb * BUF_BYTES
                           + (unsigned)(r * 1024 + h * NTHREADS + tid) * 16u;
                const float4* g = xg + (r * 1024 + h * NTHREADS + tid);
                asm volatile("cp.async.cg.shared.global [%0], [%1], 16;"
                             :: "r"(s), "l"(g));
            }
        }
        asm volatile("cp.async.commit_group;");
    }

    int bcur = 0;
    for (; q < nq; q += GRID) {
        // prefetch q+2*GRID into buffer (bcur+2)%3
        {
            int bpf = bcur + 2; if (bpf >= NBUF) bpf -= NBUF;
            int qp = q + 2 * GRID;
            int qc = qp < nq ? qp : q;
            const float4* xg = reinterpret_cast<const float4*>(X) + (size_t)qc * 4096;
#pragma unroll
            for (int r = 0; r < R4; r++) {
#pragma unroll
                for (int h = 0; h < 2; h++) {
                    unsigned s = xb_base + bpf * BUF_BYTES
                               + (unsigned)(r * 1024 + h * NTHREADS + tid) * 16u;
                    const float4* g = xg + (r * 1024 + h * NTHREADS + tid);
                    asm volatile("cp.async.cg.shared.global [%0], [%1], 16;"
                                 :: "r"(s), "l"(g));
                }
            }
            asm volatile("cp.async.commit_group;");
        }
        asm volatile("cp.async.wait_group 2;");

        const ulonglong2* xb2 =
            reinterpret_cast<const ulonglong2*>(xbuf + bcur * (R4 * DDIM));

        // pull x into registers ONCE for the whole iteration
        u64 xr[R4][4];
#pragma unroll
        for (int r = 0; r < R4; r++) {
            ulonglong2 xa = xb2[r * 1024 + tid];
            ulonglong2 xc = xb2[r * 1024 + tid + NTHREADS];
            xr[r][0] = xa.x; xr[r][1] = xa.y;
            xr[r][2] = xc.x; xr[r][3] = xc.y;
        }

        // per-row dots + 9-shfl butterfly (val stays at 8 regs)
#pragma unroll
        for (int r = 0; r < R4; r++) {
            float val[8];
#pragma unroll
            for (int i = 0; i < 8; i++) {
                u64 a0 = ffma2(xr[r][0], up[i][0], 0ull);
                u64 a1 = ffma2(xr[r][1], up[i][1], 0ull);
                a0 = ffma2(xr[r][2], up[i][2], a0);
                a1 = ffma2(xr[r][3], up[i][3], a1);
                float l0, h0, l1, h1;
                unpack2(a0, l0, h0);
                unpack2(a1, l1, h1);
                val[i] = (l0 + h0) + (l1 + h1);
            }
            // 3-stage multi-value butterfly over lane bits 0-2
#pragma unroll
            for (int s = 0; s < 3; s++) {
                const int m = 1 << s;
                const int h = 4 >> s;
#pragma unroll
                for (int k = 0; k < h; k++) {
                    float send = (lane & m) ? val[k] : val[k + h];
                    float rec  = __shfl_xor_sync(0xffffffffu, send, m);
                    float keep = (lane & m) ? val[k + h] : val[k];
                    val[k] = keep + rec;
                }
            }
            // fold the four 8-lane groups
            val[0] += __shfl_xor_sync(0xffffffffu, val[0], 8);
            val[0] += __shfl_xor_sync(0xffffffffu, val[0], 16);
            // lane holds c_partial[br3] for row r (replicated x4); 8 lanes publish
            if (lane < 8)
                wsum[warp * 32 + r * 8 + br3] = val[0];
        }
        __syncthreads();

        // warp 0: finish cross-warp reduction (c), apply S -> d,
        // publish negated duplicated f32x2 pairs
        if (warp == 0) {
            float c = 0.f;
#pragma unroll
            for (int w = 0; w < 16; w++) c += wsum[w * 32 + lane];
            const int i = lane & 7;
            float d = 0.f;
#pragma unroll
            for (int j = 0; j < 8; j++) {
                float cj = __shfl_sync(0xffffffffu, c, (lane & 24) + j);
                d += Ssh[i * 8 + j] * cj;
            }
            reinterpret_cast<u64*>(dsh2)[lane] = pack2(-d, -d);  // [row*8+i]
        }
        __syncthreads();

        // rank-8 update on register-resident x + streaming store
        {
            const ulonglong2* dq = reinterpret_cast<const ulonglong2*>(dsh2);
            float4* y4 = reinterpret_cast<float4*>(Y) + (size_t)q * 4096;
#pragma unroll
            for (int r = 0; r < R4; r++) {
                ulonglong2 p0 = dq[r * 4 + 0];
                ulonglong2 p1 = dq[r * 4 + 1];
                ulonglong2 p2 = dq[r * 4 + 2];
                ulonglong2 p3 = dq[r * 4 + 3];
                u64 nd[8] = {p0.x, p0.y, p1.x, p1.y, p2.x, p2.y, p3.x, p3.y};
#pragma unroll
                for (int i = 0; i < 8; i++) {
                    xr[r][0] = ffma2(nd[i], up[i][0], xr[r][0]);
                    xr[r][1] = ffma2(nd[i], up[i][1], xr[r][1]);
                    xr[r][2] = ffma2(nd[i], up[i][2], xr[r][2]);
                    xr[r][3] = ffma2(nd[i], up[i][3], xr[r][3]);
                }
                float4 o0, o1;
                unpack2(xr[r][0], o0.x, o0.y); unpack2(xr[r][1], o0.z, o0.w);
                unpack2(xr[r][2], o1.x, o1.y); unpack2(xr[r][3], o1.z, o1.w);
                __stcs(&y4[r * 1024 + tid], o0);
                __stcs(&y4[r * 1024 + tid + NTHREADS], o1);
            }
        }

        if (++bcur == NBUF) bcur = 0;
    }
}

extern "C" void kernel_launch(void* const* d_in, const int* in_sizes, int n_in,
                              void* d_out, int out_size) {
    const float* X = (const float*)d_in[0];      // (4, 2048, 4096) fp32
    const float* hra_u = (const float*)d_in[1];  // (4096, 8) fp32
    float* Y = (float*)d_out;

    const int nrows = in_sizes[0] / DDIM;        // 8192
    const int nq = nrows / R4;                   // 2048

    const size_t smem_bytes =
        (NBUF * R4 * DDIM + 16 * 32 + 64 + 64 + 36 + 8) * sizeof(float);
    cudaFuncSetAttribute(hra_kernel,
                         cudaFuncAttributeMaxDynamicSharedMemorySize,
                         (int)smem_bytes);

    hra_kernel<<<GRID, NTHREADS, smem_bytes>>>(X, hra_u, Y, nq);
}